// round 3
// baseline (speedup 1.0000x reference)
#include <cuda_runtime.h>
#include <math.h>

// Problem dims (fixed by the reference)
#define BB 4
#define LL 1024
#define DD 1024
#define HH 16
#define HDD 64
#define MM (BB * LL)   // 4096

typedef unsigned long long u64;

// Scratch in device globals (allocation is forbidden).
__device__ float g_q[BB * HH * LL * HDD];
__device__ float g_k[BB * HH * LL * HDD];
__device__ float g_v[BB * HH * LL * HDD];
__device__ float g_o[BB * HH * LL * HDD];

// ---- packed fp32x2 helpers (exact dual-fp32, PTX-only instruction) ----
__device__ __forceinline__ u64 ffma2(u64 a, u64 b, u64 c) {
    u64 d;
    asm("fma.rn.f32x2 %0, %1, %2, %3;" : "=l"(d) : "l"(a), "l"(b), "l"(c));
    return d;
}
__device__ __forceinline__ u64 fmul2(u64 a, u64 b) {
    u64 d;
    asm("mul.rn.f32x2 %0, %1, %2;" : "=l"(d) : "l"(a), "l"(b));
    return d;
}
__device__ __forceinline__ u64 pack2(float lo, float hi) {
    u64 d;
    asm("mov.b64 %0, {%1, %2};" : "=l"(d) : "f"(lo), "f"(hi));
    return d;
}
__device__ __forceinline__ float lo2(u64 v) { return __uint_as_float((unsigned)v); }
__device__ __forceinline__ float hi2(u64 v) { return __uint_as_float((unsigned)(v >> 32)); }

// Index helper: MODE 0 = plain row-major [M, D]; MODE 1 = [B, H, L, HD]
template <int MODE>
__device__ __forceinline__ int io_index(int m, int k) {
    if (MODE == 0) {
        return m * DD + k;
    } else {
        int b = m >> 10;
        int l = m & 1023;
        int h = k >> 6;
        int d = k & 63;
        return (((b * HH + h) * LL) + l) * HDD + d;
    }
}

#define SA  66    // k-major A tile row stride (floats), even -> LDS.64 aligned
#define SBD 132   // duplicated B tile row stride (floats), mult of 4 -> STS.128 ok

// C[M,N] = A[M,K] * W[N,K]^T + bias[N]
// 64x64 tile, BK=16, 256 threads. Packed f32x2 inner loop:
//   a = row-pair LDS.64 from k-major As_t; b = duplicated scalar LDS.64 from Bs_dup.
// Up to 3 independent GEMMs selected by blockIdx.z.
template <int IN_MODE, int OUT_MODE>
__global__ __launch_bounds__(256) void gemm2_kernel(
    const float* __restrict__ A0, const float* __restrict__ W0, const float* __restrict__ bias0, float* __restrict__ C0,
    const float* __restrict__ A1, const float* __restrict__ W1, const float* __restrict__ bias1, float* __restrict__ C1,
    const float* __restrict__ A2, const float* __restrict__ W2, const float* __restrict__ bias2, float* __restrict__ C2)
{
    const float* A = A0; const float* W = W0; const float* bias = bias0; float* C = C0;
    if (blockIdx.z == 1) { A = A1; W = W1; bias = bias1; C = C1; }
    else if (blockIdx.z == 2) { A = A2; W = W2; bias = bias2; C = C2; }

    __shared__ __align__(16) float As_t[16][SA];    // [k][m]
    __shared__ __align__(16) float Bs_d[16][SBD];   // [k][2n] duplicated

    const int m0 = blockIdx.y << 6;
    const int n0 = blockIdx.x << 6;
    const int tid = threadIdx.x;
    const int tx = tid & 15;
    const int ty = tid >> 4;
    const int lr = tid >> 2;          // 0..63
    const int lc = (tid & 3) << 2;    // {0,4,8,12}

    u64 acc[2][4] = {};   // [row-pair][col], packed over row pairs (2ty,2ty+1)/(2ty+32,2ty+33)

    for (int k0 = 0; k0 < DD; k0 += 16) {
        const float4 av = *(const float4*)(A + io_index<IN_MODE>(m0 + lr, k0 + lc));
        const float4 bv = *(const float4*)(W + (n0 + lr) * DD + (k0 + lc));
        __syncthreads();
        As_t[lc + 0][lr] = av.x;
        As_t[lc + 1][lr] = av.y;
        As_t[lc + 2][lr] = av.z;
        As_t[lc + 3][lr] = av.w;
        *(float2*)&Bs_d[lc + 0][2 * lr] = make_float2(bv.x, bv.x);
        *(float2*)&Bs_d[lc + 1][2 * lr] = make_float2(bv.y, bv.y);
        *(float2*)&Bs_d[lc + 2][2 * lr] = make_float2(bv.z, bv.z);
        *(float2*)&Bs_d[lc + 3][2 * lr] = make_float2(bv.w, bv.w);
        __syncthreads();

        #pragma unroll
        for (int kk = 0; kk < 16; ++kk) {
            const u64 a0 = *(const u64*)&As_t[kk][2 * ty];
            const u64 a1 = *(const u64*)&As_t[kk][2 * ty + 32];
            const u64 b0 = *(const u64*)&Bs_d[kk][4 * tx];
            const u64 b1 = *(const u64*)&Bs_d[kk][4 * tx + 2];
            const u64 b2 = *(const u64*)&Bs_d[kk][4 * tx + 64];
            const u64 b3 = *(const u64*)&Bs_d[kk][4 * tx + 66];
            acc[0][0] = ffma2(a0, b0, acc[0][0]);
            acc[1][0] = ffma2(a1, b0, acc[1][0]);
            acc[0][1] = ffma2(a0, b1, acc[0][1]);
            acc[1][1] = ffma2(a1, b1, acc[1][1]);
            acc[0][2] = ffma2(a0, b2, acc[0][2]);
            acc[1][2] = ffma2(a1, b2, acc[1][2]);
            acc[0][3] = ffma2(a0, b3, acc[0][3]);
            acc[1][3] = ffma2(a1, b3, acc[1][3]);
        }
    }

    // Epilogue: cols {2tx, 2tx+1, 2tx+32, 2tx+33}
    float bj[4];
    bj[0] = bias[n0 + 2 * tx];
    bj[1] = bias[n0 + 2 * tx + 1];
    bj[2] = bias[n0 + 2 * tx + 32];
    bj[3] = bias[n0 + 2 * tx + 33];

    #pragma unroll
    for (int pi = 0; pi < 2; ++pi) {
        const int rbase = 2 * ty + 32 * pi;
        #pragma unroll
        for (int h = 0; h < 2; ++h) {   // lo/hi of the packed pair
            const int m = m0 + rbase + h;
            float v0 = (h ? hi2(acc[pi][0]) : lo2(acc[pi][0])) + bj[0];
            float v1 = (h ? hi2(acc[pi][1]) : lo2(acc[pi][1])) + bj[1];
            float v2 = (h ? hi2(acc[pi][2]) : lo2(acc[pi][2])) + bj[2];
            float v3 = (h ? hi2(acc[pi][3]) : lo2(acc[pi][3])) + bj[3];
            *(float2*)&C[io_index<OUT_MODE>(m, n0 + 2 * tx)]      = make_float2(v0, v1);
            *(float2*)&C[io_index<OUT_MODE>(m, n0 + 2 * tx + 32)] = make_float2(v2, v3);
        }
    }
}

// Flash attention, 64-row q tiles, HD=64, causal, packed f32x2 math.
// Shared: Qs_t[64][SA] (d-major), Ks_d[64][SBD] (d-major, dup over keys),
//         Vs_d[64][SBD] (key-major, dup over d), Ps_t[64][SA] (key-major [c][r]).
__global__ __launch_bounds__(256) void attn2_kernel()
{
    extern __shared__ __align__(16) float sm[];
    float* Qs = sm;                      // 64*SA
    float* Ks = Qs + 64 * SA;            // 64*SBD
    float* Vs = Ks + 64 * SBD;           // 64*SBD
    float* Ps = Vs + 64 * SBD;           // 64*SA

    const int bh = blockIdx.y;
    const int qt = blockIdx.x;
    const int q0 = qt << 6;

    const float* __restrict__ Qg = g_q + bh * (LL * HDD);
    const float* __restrict__ Kg = g_k + bh * (LL * HDD);
    const float* __restrict__ Vg = g_v + bh * (LL * HDD);

    const int tid = threadIdx.x;
    const int tx = tid & 15;
    const int ty = tid >> 4;

    // Load Q tile transposed: Qs[d][r]
    for (int idx = tid; idx < 64 * 16; idx += 256) {
        const int r = idx >> 4;
        const int c4 = (idx & 15) << 2;
        const float4 qv = *(const float4*)&Qg[(q0 + r) * HDD + c4];
        Qs[(c4 + 0) * SA + r] = qv.x;
        Qs[(c4 + 1) * SA + r] = qv.y;
        Qs[(c4 + 2) * SA + r] = qv.z;
        Qs[(c4 + 3) * SA + r] = qv.w;
    }

    u64 acc[2][4] = {};         // O accumulator, packed over row pairs
    float mrow[4], lrow[4];
    #pragma unroll
    for (int i = 0; i < 4; ++i) { mrow[i] = -1e30f; lrow[i] = 0.0f; }

    for (int kt = 0; kt <= qt; ++kt) {
        const int k0 = kt << 6;

        __syncthreads();   // prior PV readers done before K/V/P overwrite
        for (int idx = tid; idx < 64 * 16; idx += 256) {
            const int r = idx >> 4;            // key index within tile
            const int c4 = (idx & 15) << 2;    // d
            const float4 kv = *(const float4*)&Kg[(k0 + r) * HDD + c4];
            const float4 vv = *(const float4*)&Vg[(k0 + r) * HDD + c4];
            *(float2*)&Ks[(c4 + 0) * SBD + 2 * r] = make_float2(kv.x, kv.x);
            *(float2*)&Ks[(c4 + 1) * SBD + 2 * r] = make_float2(kv.y, kv.y);
            *(float2*)&Ks[(c4 + 2) * SBD + 2 * r] = make_float2(kv.z, kv.z);
            *(float2*)&Ks[(c4 + 3) * SBD + 2 * r] = make_float2(kv.w, kv.w);
            *(float4*)&Vs[r * SBD + 2 * c4]     = make_float4(vv.x, vv.x, vv.y, vv.y);
            *(float4*)&Vs[r * SBD + 2 * c4 + 4] = make_float4(vv.z, vv.z, vv.w, vv.w);
        }
        __syncthreads();

        // S = Q K^T, packed over q-row pairs, cols {2tx,2tx+1,2tx+32,2tx+33}
        u64 sp[2][4] = {};
        #pragma unroll 8
        for (int d = 0; d < 64; ++d) {
            const u64 a0 = *(const u64*)&Qs[d * SA + 2 * ty];
            const u64 a1 = *(const u64*)&Qs[d * SA + 2 * ty + 32];
            const u64 b0 = *(const u64*)&Ks[d * SBD + 4 * tx];
            const u64 b1 = *(const u64*)&Ks[d * SBD + 4 * tx + 2];
            const u64 b2 = *(const u64*)&Ks[d * SBD + 4 * tx + 64];
            const u64 b3 = *(const u64*)&Ks[d * SBD + 4 * tx + 66];
            sp[0][0] = ffma2(a0, b0, sp[0][0]);
            sp[1][0] = ffma2(a1, b0, sp[1][0]);
            sp[0][1] = ffma2(a0, b1, sp[0][1]);
            sp[1][1] = ffma2(a1, b1, sp[1][1]);
            sp[0][2] = ffma2(a0, b2, sp[0][2]);
            sp[1][2] = ffma2(a1, b2, sp[1][2]);
            sp[0][3] = ffma2(a0, b3, sp[0][3]);
            sp[1][3] = ffma2(a1, b3, sp[1][3]);
        }

        // Unpack to scalars: rows {2ty, 2ty+1, 2ty+32, 2ty+33}
        float s[4][4];
        #pragma unroll
        for (int j = 0; j < 4; ++j) {
            s[0][j] = lo2(sp[0][j]);
            s[1][j] = hi2(sp[0][j]);
            s[2][j] = lo2(sp[1][j]);
            s[3][j] = hi2(sp[1][j]);
        }

        const int ri[4] = {2 * ty, 2 * ty + 1, 2 * ty + 32, 2 * ty + 33};
        const int cj[4] = {2 * tx, 2 * tx + 1, 2 * tx + 32, 2 * tx + 33};

        // Scale + causal mask
        #pragma unroll
        for (int i = 0; i < 4; ++i) {
            const int qi = q0 + ri[i];
            #pragma unroll
            for (int j = 0; j < 4; ++j) {
                const int ki = k0 + cj[j];
                s[i][j] = (ki <= qi) ? s[i][j] * 0.125f : -1e30f;
            }
        }

        // Online softmax per row (reduce over 16 tx lanes)
        float alpha[4];
        #pragma unroll
        for (int i = 0; i < 4; ++i) {
            float mx = fmaxf(fmaxf(s[i][0], s[i][1]), fmaxf(s[i][2], s[i][3]));
            #pragma unroll
            for (int off = 8; off >= 1; off >>= 1)
                mx = fmaxf(mx, __shfl_xor_sync(0xffffffffu, mx, off));
            const float mnew = fmaxf(mrow[i], mx);
            alpha[i] = __expf(mrow[i] - mnew);
            float rsum = 0.0f;
            #pragma unroll
            for (int j = 0; j < 4; ++j) {
                const float p = __expf(s[i][j] - mnew);
                s[i][j] = p;
                rsum += p;
            }
            #pragma unroll
            for (int off = 8; off >= 1; off >>= 1)
                rsum += __shfl_xor_sync(0xffffffffu, rsum, off);
            lrow[i] = lrow[i] * alpha[i] + rsum;
            mrow[i] = mnew;
        }

        // Packed alpha rescale of O accumulator
        const u64 al0 = pack2(alpha[0], alpha[1]);
        const u64 al1 = pack2(alpha[2], alpha[3]);
        #pragma unroll
        for (int j = 0; j < 4; ++j) {
            acc[0][j] = fmul2(acc[0][j], al0);
            acc[1][j] = fmul2(acc[1][j], al1);
        }

        // Stage P transposed: Ps[c][r], row pairs contiguous
        #pragma unroll
        for (int j = 0; j < 4; ++j) {
            *(float2*)&Ps[cj[j] * SA + 2 * ty]      = make_float2(s[0][j], s[1][j]);
            *(float2*)&Ps[cj[j] * SA + 2 * ty + 32] = make_float2(s[2][j], s[3][j]);
        }
        __syncthreads();

        // O += P V, packed over q-row pairs; output cols {2tx,2tx+1,2tx+32,2tx+33}
        #pragma unroll 8
        for (int c = 0; c < 64; ++c) {
            const u64 p0 = *(const u64*)&Ps[c * SA + 2 * ty];
            const u64 p1 = *(const u64*)&Ps[c * SA + 2 * ty + 32];
            const u64 v0 = *(const u64*)&Vs[c * SBD + 4 * tx];
            const u64 v1 = *(const u64*)&Vs[c * SBD + 4 * tx + 2];
            const u64 v2 = *(const u64*)&Vs[c * SBD + 4 * tx + 64];
            const u64 v3 = *(const u64*)&Vs[c * SBD + 4 * tx + 66];
            acc[0][0] = ffma2(p0, v0, acc[0][0]);
            acc[1][0] = ffma2(p1, v0, acc[1][0]);
            acc[0][1] = ffma2(p0, v1, acc[0][1]);
            acc[1][1] = ffma2(p1, v1, acc[1][1]);
            acc[0][2] = ffma2(p0, v2, acc[0][2]);
            acc[1][2] = ffma2(p1, v2, acc[1][2]);
            acc[0][3] = ffma2(p0, v3, acc[0][3]);
            acc[1][3] = ffma2(p1, v3, acc[1][3]);
        }
    }

    // Normalize and write [B,H,L,HD]
    float* Og = g_o + bh * (LL * HDD);
    const float inv0 = 1.0f / lrow[0];
    const float inv1 = 1.0f / lrow[1];
    const float inv2 = 1.0f / lrow[2];
    const float inv3 = 1.0f / lrow[3];

    {
        const int mA = q0 + 2 * ty;
        const int mB = q0 + 2 * ty + 1;
        const int mC = q0 + 2 * ty + 32;
        const int mD = q0 + 2 * ty + 33;
        *(float2*)&Og[mA * HDD + 2 * tx]      = make_float2(lo2(acc[0][0]) * inv0, lo2(acc[0][1]) * inv0);
        *(float2*)&Og[mA * HDD + 2 * tx + 32] = make_float2(lo2(acc[0][2]) * inv0, lo2(acc[0][3]) * inv0);
        *(float2*)&Og[mB * HDD + 2 * tx]      = make_float2(hi2(acc[0][0]) * inv1, hi2(acc[0][1]) * inv1);
        *(float2*)&Og[mB * HDD + 2 * tx + 32] = make_float2(hi2(acc[0][2]) * inv1, hi2(acc[0][3]) * inv1);
        *(float2*)&Og[mC * HDD + 2 * tx]      = make_float2(lo2(acc[1][0]) * inv2, lo2(acc[1][1]) * inv2);
        *(float2*)&Og[mC * HDD + 2 * tx + 32] = make_float2(lo2(acc[1][2]) * inv2, lo2(acc[1][3]) * inv2);
        *(float2*)&Og[mD * HDD + 2 * tx]      = make_float2(hi2(acc[1][0]) * inv3, hi2(acc[1][1]) * inv3);
        *(float2*)&Og[mD * HDD + 2 * tx + 32] = make_float2(hi2(acc[1][2]) * inv3, hi2(acc[1][3]) * inv3);
    }
}

extern "C" void kernel_launch(void* const* d_in, const int* in_sizes, int n_in,
                              void* d_out, int out_size)
{
    (void)in_sizes; (void)n_in; (void)out_size;

    const float* key   = (const float*)d_in[0];
    const float* value = (const float*)d_in[1];
    const float* query = (const float*)d_in[2];
    const float* Wk    = (const float*)d_in[3];
    const float* bk    = (const float*)d_in[4];
    const float* Wq    = (const float*)d_in[5];
    const float* bq    = (const float*)d_in[6];
    const float* Wv    = (const float*)d_in[7];
    const float* bv    = (const float*)d_in[8];
    const float* Wp    = (const float*)d_in[9];
    const float* bp    = (const float*)d_in[10];
    float* out = (float*)d_out;

    float *q_p, *k_p, *v_p, *o_p;
    cudaGetSymbolAddress((void**)&q_p, g_q);
    cudaGetSymbolAddress((void**)&k_p, g_k);
    cudaGetSymbolAddress((void**)&v_p, g_v);
    cudaGetSymbolAddress((void**)&o_p, g_o);

    // Fused Q/K/V projections -> [B,H,L,HD]
    gemm2_kernel<0, 1><<<dim3(DD / 64, MM / 64, 3), 256>>>(
        query, Wq, bq, q_p,
        key,   Wk, bk, k_p,
        value, Wv, bv, v_p);

    // Attention
    constexpr int SMEM = 64 * (SA + SBD + SBD + SA) * (int)sizeof(float); // 101376
    cudaFuncSetAttribute(attn2_kernel, cudaFuncAttributeMaxDynamicSharedMemorySize, SMEM);
    attn2_kernel<<<dim3(LL / 64, BB * HH), 256, SMEM>>>();

    // Output projection: gather [B,H,L,HD] -> [B,L,D]
    gemm2_kernel<1, 0><<<dim3(DD / 64, MM / 64, 1), 256>>>(
        o_p, Wp, bp, out,
        o_p, Wp, bp, out,
        o_p, Wp, bp, out);
}

// round 7
// speedup vs baseline: 5.0958x; 5.0958x over previous
#include <cuda_runtime.h>
#include <cstdint>
#include <math.h>

// Problem dims (fixed by the reference)
#define BB 4
#define LL 1024
#define DD 1024
#define HH 16
#define HDD 64
#define MM (BB * LL)   // 4096

// Scratch in device globals (allocation is forbidden).
__device__ __align__(16) float g_q[BB * HH * LL * HDD];
__device__ __align__(16) float g_k[BB * HH * LL * HDD];
__device__ __align__(16) float g_v[BB * HH * LL * HDD];
__device__ __align__(16) float g_o[BB * HH * LL * HDD];

// ---- tf32 helpers (sm_80+ portable; compiles for base sm_103) ----
__device__ __forceinline__ float to_tf32(float x) {
    float y;
    asm("cvt.rna.tf32.f32 %0, %1;" : "=f"(y) : "f"(x));
    return y;
}
__device__ __forceinline__ void mma_tf32(float* d, const uint32_t* a, const uint32_t* b) {
    asm volatile(
        "mma.sync.aligned.m16n8k8.row.col.f32.tf32.tf32.f32 "
        "{%0,%1,%2,%3}, {%4,%5,%6,%7}, {%8,%9}, {%0,%1,%2,%3};"
        : "+f"(d[0]), "+f"(d[1]), "+f"(d[2]), "+f"(d[3])
        : "r"(a[0]), "r"(a[1]), "r"(a[2]), "r"(a[3]), "r"(b[0]), "r"(b[1]));
}

// Index helper: MODE 0 = row-major [M, D]; MODE 1 = [B, H, L, HD]
template <int MODE>
__device__ __forceinline__ int io_index(int m, int k) {
    if (MODE == 0) {
        return m * DD + k;
    } else {
        int b = m >> 10;
        int l = m & 1023;
        int h = k >> 6;
        int d = k & 63;
        return (((b * HH + h) * LL) + l) * HDD + d;
    }
}

// ---------------- tensor-core tf32 GEMM ----------------
// C[M,N] = A[M,K] * W[N,K]^T + bias[N]   (torch Linear)
// CTA 128x128, BK=32, 8 warps (2 M x 4 N), warp tile 64x32 via m16n8k8.
// Smem row stride 36 floats: LDS.32 frag loads conflict-free (banks 4g+l),
// STS.128 staging at 4-wavefront optimum. Up to 3 GEMMs via blockIdx.z.

#define BKC 32
#define SSTR 36   // smem row stride (floats)

template <int IN_MODE, int OUT_MODE>
__global__ __launch_bounds__(256, 2) void gemm_mma_kernel(
    const float* __restrict__ A0, const float* __restrict__ W0, const float* __restrict__ bias0, float* __restrict__ C0,
    const float* __restrict__ A1, const float* __restrict__ W1, const float* __restrict__ bias1, float* __restrict__ C1,
    const float* __restrict__ A2, const float* __restrict__ W2, const float* __restrict__ bias2, float* __restrict__ C2)
{
    const float* A = A0; const float* W = W0; const float* bias = bias0; float* C = C0;
    if (blockIdx.z == 1) { A = A1; W = W1; bias = bias1; C = C1; }
    else if (blockIdx.z == 2) { A = A2; W = W2; bias = bias2; C = C2; }

    __shared__ __align__(16) float As[128 * SSTR];   // [m][k']
    __shared__ __align__(16) float Bs[128 * SSTR];   // [n][k']

    const int tid = threadIdx.x;
    const int wid = tid >> 5;
    const int lane = tid & 31;
    const int g = lane >> 2;    // group row 0..7
    const int l = lane & 3;     // thread-in-group 0..3
    const int wm = wid & 1;     // warp M index (0..1)
    const int wn = wid >> 1;    // warp N index (0..3)

    const int m0 = blockIdx.y << 7;
    const int n0 = blockIdx.x << 7;

    // Staging coords: 1024 float4 per tile, 256 threads x 4.
    const int srow[4] = { (tid + 0) >> 3, (tid + 256) >> 3, (tid + 512) >> 3, (tid + 768) >> 3 };
    const int scol = (tid & 7) << 2;

    float acc[4][4][4] = {};   // [mt][nt][frag]

    for (int chunk = 0; chunk < DD / BKC; ++chunk) {
        const int k0 = chunk * BKC;

        __syncthreads();   // previous compute done before overwrite
        #pragma unroll
        for (int p = 0; p < 4; ++p) {
            const int row = srow[p];
            float4 av = *(const float4*)(A + io_index<IN_MODE>(m0 + row, k0 + scol));
            float4 bv = *(const float4*)(W + (n0 + row) * DD + (k0 + scol));
            av.x = to_tf32(av.x); av.y = to_tf32(av.y); av.z = to_tf32(av.z); av.w = to_tf32(av.w);
            bv.x = to_tf32(bv.x); bv.y = to_tf32(bv.y); bv.z = to_tf32(bv.z); bv.w = to_tf32(bv.w);
            *(float4*)&As[row * SSTR + scol] = av;
            *(float4*)&Bs[row * SSTR + scol] = bv;
        }
        __syncthreads();

        #pragma unroll
        for (int s = 0; s < 4; ++s) {
            const int ks = s << 3;

            uint32_t afr[4][4];
            #pragma unroll
            for (int mt = 0; mt < 4; ++mt) {
                const int rb = wm * 64 + mt * 16;
                afr[mt][0] = __float_as_uint(As[(rb + g) * SSTR + ks + l]);
                afr[mt][1] = __float_as_uint(As[(rb + g + 8) * SSTR + ks + l]);
                afr[mt][2] = __float_as_uint(As[(rb + g) * SSTR + ks + l + 4]);
                afr[mt][3] = __float_as_uint(As[(rb + g + 8) * SSTR + ks + l + 4]);
            }
            uint32_t bfr[4][2];
            #pragma unroll
            for (int nt = 0; nt < 4; ++nt) {
                const int nb = wn * 32 + nt * 8;
                bfr[nt][0] = __float_as_uint(Bs[(nb + g) * SSTR + ks + l]);
                bfr[nt][1] = __float_as_uint(Bs[(nb + g) * SSTR + ks + l + 4]);
            }
            #pragma unroll
            for (int mt = 0; mt < 4; ++mt)
                #pragma unroll
                for (int nt = 0; nt < 4; ++nt)
                    mma_tf32(acc[mt][nt], afr[mt], bfr[nt]);
        }
    }

    // Epilogue: c0=(g,2l) c1=(g,2l+1) c2=(g+8,2l) c3=(g+8,2l+1) per 16x8 tile.
    #pragma unroll
    for (int nt = 0; nt < 4; ++nt) {
        const int n = n0 + wn * 32 + nt * 8 + 2 * l;
        const float b0 = bias[n];
        const float b1 = bias[n + 1];
        #pragma unroll
        for (int mt = 0; mt < 4; ++mt) {
            const int mlo = m0 + wm * 64 + mt * 16 + g;
            *(float2*)(C + io_index<OUT_MODE>(mlo, n)) =
                make_float2(acc[mt][nt][0] + b0, acc[mt][nt][1] + b1);
            *(float2*)(C + io_index<OUT_MODE>(mlo + 8, n)) =
                make_float2(acc[mt][nt][2] + b0, acc[mt][nt][3] + b1);
        }
    }
}

// ---------------- Flash attention (known-good scalar R1 version) ----------------
__global__ __launch_bounds__(256) void attn_kernel()
{
    extern __shared__ float sm[];
    float* Qs = sm;                     // 64*64
    float* Ks = Qs + 64 * 64;           // 64*68 (padded)
    float* Vs = Ks + 64 * 68;           // 64*64
    float* Ps = Vs + 64 * 64;           // 64*64

    const int bh = blockIdx.y;
    const int qt = blockIdx.x;
    const int q0 = qt << 6;

    const float* __restrict__ Qg = g_q + bh * (LL * HDD);
    const float* __restrict__ Kg = g_k + bh * (LL * HDD);
    const float* __restrict__ Vg = g_v + bh * (LL * HDD);

    const int tid = threadIdx.x;
    const int tx = tid & 15;
    const int ty = tid >> 4;

    for (int idx = tid; idx < 64 * 16; idx += 256) {
        const int r = idx >> 4;
        const int c4 = (idx & 15) << 2;
        *(float4*)&Qs[r * 64 + c4] = *(const float4*)&Qg[(q0 + r) * HDD + c4];
    }

    float acc[4][4] = {};
    float mrow[4], lrow[4];
    #pragma unroll
    for (int i = 0; i < 4; ++i) { mrow[i] = -1e30f; lrow[i] = 0.0f; }

    for (int kt = 0; kt <= qt; ++kt) {
        const int k0 = kt << 6;

        __syncthreads();
        for (int idx = tid; idx < 64 * 16; idx += 256) {
            const int r = idx >> 4;
            const int c4 = (idx & 15) << 2;
            *(float4*)&Ks[r * 68 + c4] = *(const float4*)&Kg[(k0 + r) * HDD + c4];
            *(float4*)&Vs[r * 64 + c4] = *(const float4*)&Vg[(k0 + r) * HDD + c4];
        }
        __syncthreads();

        float s[4][4] = {};
        #pragma unroll 8
        for (int d = 0; d < 64; ++d) {
            float a[4], b[4];
            #pragma unroll
            for (int i = 0; i < 4; ++i) a[i] = Qs[(ty + 16 * i) * 64 + d];
            #pragma unroll
            for (int j = 0; j < 4; ++j) b[j] = Ks[(tx + 16 * j) * 68 + d];
            #pragma unroll
            for (int i = 0; i < 4; ++i)
                #pragma unroll
                for (int j = 0; j < 4; ++j)
                    s[i][j] = fmaf(a[i], b[j], s[i][j]);
        }

        #pragma unroll
        for (int i = 0; i < 4; ++i) {
            const int qi = q0 + ty + 16 * i;
            #pragma unroll
            for (int j = 0; j < 4; ++j) {
                const int ki = k0 + tx + 16 * j;
                s[i][j] = (ki <= qi) ? s[i][j] * 0.125f : -1e30f;
            }
        }

        #pragma unroll
        for (int i = 0; i < 4; ++i) {
            float mx = fmaxf(fmaxf(s[i][0], s[i][1]), fmaxf(s[i][2], s[i][3]));
            #pragma unroll
            for (int off = 8; off >= 1; off >>= 1)
                mx = fmaxf(mx, __shfl_xor_sync(0xffffffffu, mx, off));
            const float mnew = fmaxf(mrow[i], mx);
            const float alpha = __expf(mrow[i] - mnew);
            float rsum = 0.0f;
            #pragma unroll
            for (int j = 0; j < 4; ++j) {
                const float p = __expf(s[i][j] - mnew);
                s[i][j] = p;
                rsum += p;
            }
            #pragma unroll
            for (int off = 8; off >= 1; off >>= 1)
                rsum += __shfl_xor_sync(0xffffffffu, rsum, off);
            lrow[i] = lrow[i] * alpha + rsum;
            mrow[i] = mnew;
            #pragma unroll
            for (int j = 0; j < 4; ++j) acc[i][j] *= alpha;
        }

        #pragma unroll
        for (int i = 0; i < 4; ++i)
            #pragma unroll
            for (int j = 0; j < 4; ++j)
                Ps[(ty + 16 * i) * 64 + tx + 16 * j] = s[i][j];
        __syncthreads();

        #pragma unroll 8
        for (int c = 0; c < 64; ++c) {
            float a[4], b[4];
            #pragma unroll
            for (int i = 0; i < 4; ++i) a[i] = Ps[(ty + 16 * i) * 64 + c];
            #pragma unroll
            for (int j = 0; j < 4; ++j) b[j] = Vs[c * 64 + tx + 16 * j];
            #pragma unroll
            for (int i = 0; i < 4; ++i)
                #pragma unroll
                for (int j = 0; j < 4; ++j)
                    acc[i][j] = fmaf(a[i], b[j], acc[i][j]);
        }
    }

    float* Og = g_o + bh * (LL * HDD);
    #pragma unroll
    for (int i = 0; i < 4; ++i) {
        const float inv = 1.0f / lrow[i];
        #pragma unroll
        for (int j = 0; j < 4; ++j)
            Og[(q0 + ty + 16 * i) * 64 + tx + 16 * j] = acc[i][j] * inv;
    }
}

extern "C" void kernel_launch(void* const* d_in, const int* in_sizes, int n_in,
                              void* d_out, int out_size)
{
    (void)in_sizes; (void)n_in; (void)out_size;

    const float* key   = (const float*)d_in[0];
    const float* value = (const float*)d_in[1];
    const float* query = (const float*)d_in[2];
    const float* Wk    = (const float*)d_in[3];
    const float* bk    = (const float*)d_in[4];
    const float* Wq    = (const float*)d_in[5];
    const float* bq    = (const float*)d_in[6];
    const float* Wv    = (const float*)d_in[7];
    const float* bv    = (const float*)d_in[8];
    const float* Wp    = (const float*)d_in[9];
    const float* bp    = (const float*)d_in[10];
    float* out = (float*)d_out;

    float *q_p, *k_p, *v_p, *o_p;
    cudaGetSymbolAddress((void**)&q_p, g_q);
    cudaGetSymbolAddress((void**)&k_p, g_k);
    cudaGetSymbolAddress((void**)&v_p, g_v);
    cudaGetSymbolAddress((void**)&o_p, g_o);

    // Fused Q/K/V projections -> [B,H,L,HD]  (tensor-core tf32)
    gemm_mma_kernel<0, 1><<<dim3(DD / 128, MM / 128, 3), 256>>>(
        query, Wq, bq, q_p,
        key,   Wk, bk, k_p,
        value, Wv, bv, v_p);

    // Attention (scalar fp32, known good)
    constexpr int ASMEM = (64 * 64 + 64 * 68 + 64 * 64 + 64 * 64) * (int)sizeof(float); // 66560
    cudaFuncSetAttribute(attn_kernel, cudaFuncAttributeMaxDynamicSharedMemorySize, ASMEM);
    attn_kernel<<<dim3(LL / 64, BB * HH), 256, ASMEM>>>();

    // Output projection: gather [B,H,L,HD] -> [B,L,D]  (tensor-core tf32)
    gemm_mma_kernel<1, 0><<<dim3(DD / 128, MM / 128, 1), 256>>>(
        o_p, Wp, bp, out,
        o_p, Wp, bp, out,
        o_p, Wp, bp, out);
}

// round 9
// speedup vs baseline: 7.5852x; 1.4885x over previous
#include <cuda_runtime.h>
#include <cstdint>
#include <math.h>

// Problem dims (fixed by the reference)
#define BB 4
#define LL 1024
#define DD 1024
#define HH 16
#define HDD 64
#define MM (BB * LL)   // 4096

// Scratch in device globals (allocation is forbidden).
__device__ __align__(16) float g_q[BB * HH * LL * HDD];
__device__ __align__(16) float g_k[BB * HH * LL * HDD];
__device__ __align__(16) float g_v[BB * HH * LL * HDD];
__device__ __align__(16) float g_o[BB * HH * LL * HDD];

// ---- tf32 helpers (sm_80+ portable; compiles for base sm_103) ----
__device__ __forceinline__ float to_tf32(float x) {
    float y;
    asm("cvt.rna.tf32.f32 %0, %1;" : "=f"(y) : "f"(x));
    return y;
}
__device__ __forceinline__ void mma_tf32(float* d, const uint32_t* a, const uint32_t* b) {
    asm volatile(
        "mma.sync.aligned.m16n8k8.row.col.f32.tf32.tf32.f32 "
        "{%0,%1,%2,%3}, {%4,%5,%6,%7}, {%8,%9}, {%0,%1,%2,%3};"
        : "+f"(d[0]), "+f"(d[1]), "+f"(d[2]), "+f"(d[3])
        : "r"(a[0]), "r"(a[1]), "r"(a[2]), "r"(a[3]), "r"(b[0]), "r"(b[1]));
}

// Index helper: MODE 0 = row-major [M, D]; MODE 1 = [B, H, L, HD]
template <int MODE>
__device__ __forceinline__ int io_index(int m, int k) {
    if (MODE == 0) {
        return m * DD + k;
    } else {
        int b = m >> 10;
        int l = m & 1023;
        int h = k >> 6;
        int d = k & 63;
        return (((b * HH + h) * LL) + l) * HDD + d;
    }
}

// ---------------- tensor-core tf32 GEMM (unchanged from R7 — passing) ----------------
#define BKC 32
#define SSTR 36   // smem row stride (floats)

template <int IN_MODE, int OUT_MODE>
__global__ __launch_bounds__(256, 2) void gemm_mma_kernel(
    const float* __restrict__ A0, const float* __restrict__ W0, const float* __restrict__ bias0, float* __restrict__ C0,
    const float* __restrict__ A1, const float* __restrict__ W1, const float* __restrict__ bias1, float* __restrict__ C1,
    const float* __restrict__ A2, const float* __restrict__ W2, const float* __restrict__ bias2, float* __restrict__ C2)
{
    const float* A = A0; const float* W = W0; const float* bias = bias0; float* C = C0;
    if (blockIdx.z == 1) { A = A1; W = W1; bias = bias1; C = C1; }
    else if (blockIdx.z == 2) { A = A2; W = W2; bias = bias2; C = C2; }

    __shared__ __align__(16) float As[128 * SSTR];   // [m][k']
    __shared__ __align__(16) float Bs[128 * SSTR];   // [n][k']

    const int tid = threadIdx.x;
    const int wid = tid >> 5;
    const int lane = tid & 31;
    const int g = lane >> 2;
    const int l = lane & 3;
    const int wm = wid & 1;
    const int wn = wid >> 1;

    const int m0 = blockIdx.y << 7;
    const int n0 = blockIdx.x << 7;

    const int srow[4] = { (tid + 0) >> 3, (tid + 256) >> 3, (tid + 512) >> 3, (tid + 768) >> 3 };
    const int scol = (tid & 7) << 2;

    float acc[4][4][4] = {};

    for (int chunk = 0; chunk < DD / BKC; ++chunk) {
        const int k0 = chunk * BKC;

        __syncthreads();
        #pragma unroll
        for (int p = 0; p < 4; ++p) {
            const int row = srow[p];
            float4 av = *(const float4*)(A + io_index<IN_MODE>(m0 + row, k0 + scol));
            float4 bv = *(const float4*)(W + (n0 + row) * DD + (k0 + scol));
            av.x = to_tf32(av.x); av.y = to_tf32(av.y); av.z = to_tf32(av.z); av.w = to_tf32(av.w);
            bv.x = to_tf32(bv.x); bv.y = to_tf32(bv.y); bv.z = to_tf32(bv.z); bv.w = to_tf32(bv.w);
            *(float4*)&As[row * SSTR + scol] = av;
            *(float4*)&Bs[row * SSTR + scol] = bv;
        }
        __syncthreads();

        #pragma unroll
        for (int s = 0; s < 4; ++s) {
            const int ks = s << 3;

            uint32_t afr[4][4];
            #pragma unroll
            for (int mt = 0; mt < 4; ++mt) {
                const int rb = wm * 64 + mt * 16;
                afr[mt][0] = __float_as_uint(As[(rb + g) * SSTR + ks + l]);
                afr[mt][1] = __float_as_uint(As[(rb + g + 8) * SSTR + ks + l]);
                afr[mt][2] = __float_as_uint(As[(rb + g) * SSTR + ks + l + 4]);
                afr[mt][3] = __float_as_uint(As[(rb + g + 8) * SSTR + ks + l + 4]);
            }
            uint32_t bfr[4][2];
            #pragma unroll
            for (int nt = 0; nt < 4; ++nt) {
                const int nb = wn * 32 + nt * 8;
                bfr[nt][0] = __float_as_uint(Bs[(nb + g) * SSTR + ks + l]);
                bfr[nt][1] = __float_as_uint(Bs[(nb + g) * SSTR + ks + l + 4]);
            }
            #pragma unroll
            for (int mt = 0; mt < 4; ++mt)
                #pragma unroll
                for (int nt = 0; nt < 4; ++nt)
                    mma_tf32(acc[mt][nt], afr[mt], bfr[nt]);
        }
    }

    #pragma unroll
    for (int nt = 0; nt < 4; ++nt) {
        const int n = n0 + wn * 32 + nt * 8 + 2 * l;
        const float b0 = bias[n];
        const float b1 = bias[n + 1];
        #pragma unroll
        for (int mt = 0; mt < 4; ++mt) {
            const int mlo = m0 + wm * 64 + mt * 16 + g;
            *(float2*)(C + io_index<OUT_MODE>(mlo, n)) =
                make_float2(acc[mt][nt][0] + b0, acc[mt][nt][1] + b1);
            *(float2*)(C + io_index<OUT_MODE>(mlo + 8, n)) =
                make_float2(acc[mt][nt][2] + b0, acc[mt][nt][3] + b1);
        }
    }
}

// ---------------- tensor-core tf32 flash attention ----------------
// CTA: 128 q-rows of one head; k-tiles of 64 keys. 8 warps, warp w owns
// q-rows [16w, 16w+16) -> softmax fully warp-local. S and PV via m16n8k8.
// Row strides: Q/K/P = 68 floats (>=64 data; 68 mod 32 = 4 -> frag pattern
// 4g+l covers all 32 banks), V = 72 floats (pattern 8l+g covers all banks).

#define ASTR 68
#define VSTR 72
#define ATT_SMEM ((128 * ASTR + 64 * ASTR + 64 * VSTR + 128 * ASTR) * 4)  // 105472 B

__global__ __launch_bounds__(256) void attn_mma_kernel()
{
    extern __shared__ __align__(16) float sm[];
    float* Qs = sm;                       // [128][ASTR] q-rows, tf32, pre-scaled
    float* Ks = Qs + 128 * ASTR;          // [64][ASTR]  key-rows, tf32
    float* Vs = Ks + 64 * ASTR;           // [64][VSTR]  key-rows, tf32
    float* Ps = Vs + 64 * VSTR;           // [128][ASTR] P staging (warp-private rows)

    const int bh = blockIdx.y;
    const int qt = blockIdx.x;
    const int q0 = qt << 7;

    const float* __restrict__ Qg = g_q + bh * (LL * HDD);
    const float* __restrict__ Kg = g_k + bh * (LL * HDD);
    const float* __restrict__ Vg = g_v + bh * (LL * HDD);

    const int tid = threadIdx.x;
    const int wid = tid >> 5;
    const int lane = tid & 31;
    const int g = lane >> 2;
    const int l = lane & 3;
    const int wrow = q0 + 16 * wid;       // first global q-row of this warp

    // Load Q tile [128 x 64], scale by 1/sqrt(64), convert to tf32.
    #pragma unroll
    for (int p = 0; p < 8; ++p) {
        const int idx = tid + 256 * p;
        const int r = idx >> 4;
        const int c4 = (idx & 15) << 2;
        float4 qv = *(const float4*)&Qg[(q0 + r) * HDD + c4];
        qv.x = to_tf32(qv.x * 0.125f); qv.y = to_tf32(qv.y * 0.125f);
        qv.z = to_tf32(qv.z * 0.125f); qv.w = to_tf32(qv.w * 0.125f);
        *(float4*)&Qs[r * ASTR + c4] = qv;
    }

    float acc_o[8][4] = {};              // [d-tile][frag] rows (g, g+8) x cols (2l, 2l+1)
    float m0 = -1e30f, m1 = -1e30f;      // row stats for rows wrow+g, wrow+8+g
    float l0 = 0.0f, l1 = 0.0f;

    const int nkt = 2 * qt + 2;
    for (int kt = 0; kt < nkt; ++kt) {
        const int k0 = kt << 6;

        __syncthreads();   // prior S/PV reads of Ks/Vs done
        #pragma unroll
        for (int p = 0; p < 4; ++p) {
            const int idx = tid + 256 * p;
            const int r = idx >> 4;
            const int c4 = (idx & 15) << 2;
            float4 kv = *(const float4*)&Kg[(k0 + r) * HDD + c4];
            float4 vv = *(const float4*)&Vg[(k0 + r) * HDD + c4];
            kv.x = to_tf32(kv.x); kv.y = to_tf32(kv.y); kv.z = to_tf32(kv.z); kv.w = to_tf32(kv.w);
            vv.x = to_tf32(vv.x); vv.y = to_tf32(vv.y); vv.z = to_tf32(vv.z); vv.w = to_tf32(vv.w);
            *(float4*)&Ks[r * ASTR + c4] = kv;
            *(float4*)&Vs[r * VSTR + c4] = vv;
        }
        __syncthreads();

        if (k0 > wrow + 15) continue;    // warp tile fully above diagonal

        // ---- S = Q K^T for this warp's 16 rows x 64 keys ----
        float s[8][4] = {};
        #pragma unroll
        for (int st = 0; st < 8; ++st) {
            const int ks = st << 3;
            uint32_t af[4];
            af[0] = __float_as_uint(Qs[(16 * wid + g) * ASTR + ks + l]);
            af[1] = __float_as_uint(Qs[(16 * wid + g + 8) * ASTR + ks + l]);
            af[2] = __float_as_uint(Qs[(16 * wid + g) * ASTR + ks + l + 4]);
            af[3] = __float_as_uint(Qs[(16 * wid + g + 8) * ASTR + ks + l + 4]);
            #pragma unroll
            for (int nt = 0; nt < 8; ++nt) {
                uint32_t bf[2];
                bf[0] = __float_as_uint(Ks[(nt * 8 + g) * ASTR + ks + l]);
                bf[1] = __float_as_uint(Ks[(nt * 8 + g) * ASTR + ks + l + 4]);
                mma_tf32(s[nt], af, bf);
            }
        }

        // ---- causal mask (only needed when tile straddles the diagonal) ----
        const int r0 = wrow + g;
        const int r1 = wrow + 8 + g;
        if (k0 + 63 > wrow) {
            #pragma unroll
            for (int nt = 0; nt < 8; ++nt) {
                const int c = k0 + nt * 8 + 2 * l;
                if (c > r0)     s[nt][0] = -1e30f;
                if (c + 1 > r0) s[nt][1] = -1e30f;
                if (c > r1)     s[nt][2] = -1e30f;
                if (c + 1 > r1) s[nt][3] = -1e30f;
            }
        }

        // ---- online softmax (warp-local; lanes sharing g reduce over l) ----
        float mx0 = -1e30f, mx1 = -1e30f;
        #pragma unroll
        for (int nt = 0; nt < 8; ++nt) {
            mx0 = fmaxf(mx0, fmaxf(s[nt][0], s[nt][1]));
            mx1 = fmaxf(mx1, fmaxf(s[nt][2], s[nt][3]));
        }
        #pragma unroll
        for (int off = 2; off >= 1; off >>= 1) {
            mx0 = fmaxf(mx0, __shfl_xor_sync(0xffffffffu, mx0, off));
            mx1 = fmaxf(mx1, __shfl_xor_sync(0xffffffffu, mx1, off));
        }
        const float mn0 = fmaxf(m0, mx0);
        const float mn1 = fmaxf(m1, mx1);
        const float a0 = __expf(m0 - mn0);
        const float a1 = __expf(m1 - mn1);

        float sum0 = 0.0f, sum1 = 0.0f;
        #pragma unroll
        for (int nt = 0; nt < 8; ++nt) {
            s[nt][0] = __expf(s[nt][0] - mn0); sum0 += s[nt][0];
            s[nt][1] = __expf(s[nt][1] - mn0); sum0 += s[nt][1];
            s[nt][2] = __expf(s[nt][2] - mn1); sum1 += s[nt][2];
            s[nt][3] = __expf(s[nt][3] - mn1); sum1 += s[nt][3];
        }
        #pragma unroll
        for (int off = 2; off >= 1; off >>= 1) {
            sum0 += __shfl_xor_sync(0xffffffffu, sum0, off);
            sum1 += __shfl_xor_sync(0xffffffffu, sum1, off);
        }
        l0 = l0 * a0 + sum0;
        l1 = l1 * a1 + sum1;
        m0 = mn0;
        m1 = mn1;

        #pragma unroll
        for (int nt = 0; nt < 8; ++nt) {
            acc_o[nt][0] *= a0; acc_o[nt][1] *= a0;
            acc_o[nt][2] *= a1; acc_o[nt][3] *= a1;
        }

        // ---- stage P (tf32) into warp-private Ps rows ----
        #pragma unroll
        for (int nt = 0; nt < 8; ++nt) {
            *(float2*)&Ps[(16 * wid + g) * ASTR + nt * 8 + 2 * l] =
                make_float2(to_tf32(s[nt][0]), to_tf32(s[nt][1]));
            *(float2*)&Ps[(16 * wid + g + 8) * ASTR + nt * 8 + 2 * l] =
                make_float2(to_tf32(s[nt][2]), to_tf32(s[nt][3]));
        }
        __syncwarp();   // cross-lane visibility of Ps within the warp

        // ---- O += P V ----
        #pragma unroll
        for (int st = 0; st < 8; ++st) {
            const int ks = st << 3;
            uint32_t af[4];
            af[0] = __float_as_uint(Ps[(16 * wid + g) * ASTR + ks + l]);
            af[1] = __float_as_uint(Ps[(16 * wid + g + 8) * ASTR + ks + l]);
            af[2] = __float_as_uint(Ps[(16 * wid + g) * ASTR + ks + l + 4]);
            af[3] = __float_as_uint(Ps[(16 * wid + g + 8) * ASTR + ks + l + 4]);
            #pragma unroll
            for (int nt = 0; nt < 8; ++nt) {
                uint32_t bf[2];
                bf[0] = __float_as_uint(Vs[(ks + l) * VSTR + nt * 8 + g]);
                bf[1] = __float_as_uint(Vs[(ks + l + 4) * VSTR + nt * 8 + g]);
                mma_tf32(acc_o[nt], af, bf);
            }
        }
    }

    // ---- normalize and write O rows (wrow+g, wrow+8+g) ----
    float* Og = g_o + bh * (LL * HDD);
    const float inv0 = 1.0f / l0;
    const float inv1 = 1.0f / l1;
    const int r0 = wrow + g;
    const int r1 = wrow + 8 + g;
    #pragma unroll
    for (int nt = 0; nt < 8; ++nt) {
        const int d = nt * 8 + 2 * l;
        *(float2*)&Og[r0 * HDD + d] = make_float2(acc_o[nt][0] * inv0, acc_o[nt][1] * inv0);
        *(float2*)&Og[r1 * HDD + d] = make_float2(acc_o[nt][2] * inv1, acc_o[nt][3] * inv1);
    }
}

extern "C" void kernel_launch(void* const* d_in, const int* in_sizes, int n_in,
                              void* d_out, int out_size)
{
    (void)in_sizes; (void)n_in; (void)out_size;

    const float* key   = (const float*)d_in[0];
    const float* value = (const float*)d_in[1];
    const float* query = (const float*)d_in[2];
    const float* Wk    = (const float*)d_in[3];
    const float* bk    = (const float*)d_in[4];
    const float* Wq    = (const float*)d_in[5];
    const float* bq    = (const float*)d_in[6];
    const float* Wv    = (const float*)d_in[7];
    const float* bv    = (const float*)d_in[8];
    const float* Wp    = (const float*)d_in[9];
    const float* bp    = (const float*)d_in[10];
    float* out = (float*)d_out;

    float *q_p, *k_p, *v_p, *o_p;
    cudaGetSymbolAddress((void**)&q_p, g_q);
    cudaGetSymbolAddress((void**)&k_p, g_k);
    cudaGetSymbolAddress((void**)&v_p, g_v);
    cudaGetSymbolAddress((void**)&o_p, g_o);

    // Fused Q/K/V projections -> [B,H,L,HD]  (tensor-core tf32)
    gemm_mma_kernel<0, 1><<<dim3(DD / 128, MM / 128, 3), 256>>>(
        query, Wq, bq, q_p,
        key,   Wk, bk, k_p,
        value, Wv, bv, v_p);

    // Attention (tensor-core tf32 flash)
    cudaFuncSetAttribute(attn_mma_kernel, cudaFuncAttributeMaxDynamicSharedMemorySize, ATT_SMEM);
    attn_mma_kernel<<<dim3(LL / 128, BB * HH), 256, ATT_SMEM>>>();

    // Output projection: gather [B,H,L,HD] -> [B,L,D]  (tensor-core tf32)
    gemm_mma_kernel<1, 0><<<dim3(DD / 128, MM / 128, 1), 256>>>(
        o_p, Wp, bp, out,
        o_p, Wp, bp, out,
        o_p, Wp, bp, out);
}